// round 7
// baseline (speedup 1.0000x reference)
#include <cuda_runtime.h>

#define NMAX 8192

// Scratch — zero-initialized at module load; epilogue restores accumulator
// zeros every call so graph replays see a clean state.
__device__ int      g_cntpack[2][NMAX];   // low 16: cnt, high 16: pos_cnt
__device__ float    g_sumexp[2][NMAX];    // sum of exp(out[i]) over mask
__device__ float    g_poslog[2][NMAX];    // sum of out[i] over mask & pos
__device__ float    g_contrib[NMAX];      // per-column contribution (overwritten)
__device__ unsigned g_done;               // block-completion counter

// Row-per-warp scan: each warp owns 1024 contiguous int4 quads (half a row at
// N=8192), so the row index, outs[i], targets[i], expf and pack are computed
// ONCE per warp. Loads are fully coalesced (512B per LDG.128). Hits scatter
// into per-(side,column) accumulators with a ~12-instruction divergent path.
__global__ void __launch_bounds__(256) main_kernel(
    const int4* __restrict__ adj,
    const float* __restrict__ outs,
    const int* __restrict__ tgt,
    int rowShift)                          // log2(quads per row)
{
    const int  gtid  = blockIdx.x * blockDim.x + threadIdx.x;
    const int  gwarp = gtid >> 5;
    const int  lane  = gtid & 31;

    const long long quadBase = (long long)gwarp << 10;          // 1024 quads/warp
    const int i      = (int)(quadBase >> rowShift);             // row (warp-uniform)
    const int cqBase = (int)(quadBase & ((1 << rowShift) - 1)); // quad offset in row

    const float o    = __ldg(&outs[i]);                         // broadcast loads
    const int   p    = (__ldg(&tgt[i]) != 0) ? 1 : 0;
    const float e    = expf(o);
    const int   pack = 1 + (p << 16);

    #pragma unroll
    for (int jb = 0; jb < 4; jb++) {
        int4 vv[8];
        #pragma unroll
        for (int u = 0; u < 8; u++)
            vv[u] = __ldg(&adj[quadBase + (jb * 8 + u) * 32 + lane]);

        #pragma unroll
        for (int u = 0; u < 8; u++) {
            int4 v = vv[u];
            if ((v.x | v.y | v.z | v.w) == 0) continue;         // ~98.5% of quads

            int c = (cqBase + (jb * 8 + u) * 32 + lane) << 2;   // first column
            #pragma unroll
            for (int w = 0; w < 4; w++) {
                int val = (w == 0) ? v.x : (w == 1) ? v.y : (w == 2) ? v.z : v.w;
                int cc = c + w;
                if (val != 0 && cc != i) {
                    int side = (i < cc) ? 0 : 1;  // 0 = lower (i < k), 1 = upper
                    atomicAdd(&g_cntpack[side][cc], pack);
                    atomicAdd(&g_sumexp[side][cc], e);
                    if (p) atomicAdd(&g_poslog[side][cc], o);
                }
            }
        }
    }
}

// Single fused epilogue:
//  phase 1 (all blocks): thread t computes column t's contribution into
//    g_contrib[t] (6 independent loads, no chains) and cleans column t's
//    accumulators (same thread -> no race).
//  phase 2 (last block only, elected via g_done): gathers g_contrib[idx[k]]
//    over the K sorted entries (duplicates supply multiplicity), block-reduces,
//    publishes out[0], resets g_done.
__global__ void __launch_bounds__(256) epilogue_kernel(
    float* __restrict__ out,
    const int* __restrict__ idx,
    int N, int K)
{
    int t = blockIdx.x * blockDim.x + threadIdx.x;

    if (t < N) {
        int   pack0 = g_cntpack[0][t], pack1 = g_cntpack[1][t];
        float se0 = g_sumexp[0][t], se1 = g_sumexp[1][t];
        float pl0 = g_poslog[0][t], pl1 = g_poslog[1][t];

        int cnt0 = pack0 & 0xFFFF, pc0 = pack0 >> 16;
        int cnt1 = pack1 & 0xFFFF, pc1 = pack1 >> 16;

        float v = 0.f;
        if (cnt0 > 0 && pc0 == 1) v += (logf(se0) - pl0) / (float)cnt0;
        if (cnt1 > 0 && pc1 == 1) v += (logf(se1) - pl1) / (float)cnt1;
        g_contrib[t] = v;

        // Self-clean for the next graph replay (same thread, same column).
        g_cntpack[0][t] = 0; g_cntpack[1][t] = 0;
        g_sumexp[0][t] = 0.f; g_sumexp[1][t] = 0.f;
        g_poslog[0][t] = 0.f; g_poslog[1][t] = 0.f;
    }

    // Make this thread's writes visible before the completion count.
    __threadfence();
    __syncthreads();

    __shared__ bool isLast;
    if (threadIdx.x == 0) {
        unsigned d = atomicAdd(&g_done, 1u);
        isLast = (d == gridDim.x - 1);
    }
    __syncthreads();
    if (!isLast) return;

    __threadfence();   // acquire side: see all blocks' g_contrib writes

    float local = 0.f;
    for (int k = threadIdx.x; k < K; k += blockDim.x)
        local += g_contrib[__ldg(&idx[k])];

    #pragma unroll
    for (int s = 16; s > 0; s >>= 1)
        local += __shfl_xor_sync(0xFFFFFFFF, local, s);

    __shared__ float warpsum[8];
    int lane = threadIdx.x & 31, wid = threadIdx.x >> 5;
    if (lane == 0) warpsum[wid] = local;
    __syncthreads();
    if (wid == 0) {
        float b = (lane < 8) ? warpsum[lane] : 0.f;
        #pragma unroll
        for (int s = 4; s > 0; s >>= 1)
            b += __shfl_xor_sync(0xFFFFFFFF, b, s);
        if (lane == 0) {
            out[0] = b;
            g_done = 0;   // reset for next replay
        }
    }
}

extern "C" void kernel_launch(void* const* d_in, const int* in_sizes, int n_in,
                              void* d_out, int out_size) {
    const float* outs = (const float*)d_in[0];   // outputs  [N] f32
    const int*   tgt  = (const int*)d_in[1];     // targets  [N] i32
    const int*   adj  = (const int*)d_in[2];     // node_adj [N,N] i32
    const int*   idx  = (const int*)d_in[3];     // idx_node [K] i32 (sorted)
    int N = in_sizes[0];
    int K = in_sizes[3];
    float* out = (float*)d_out;

    // quadsPerRow = N/4 is a power of two; rowShift = log2(N/4)
    int rowShift = 0;
    for (int t = N >> 2; t > 1; t >>= 1) rowShift++;

    // Each warp: 1024 quads; each block (8 warps): 8192 quads.
    long long totalQuads = ((long long)N * N) >> 2;
    int blocks = (int)(totalQuads >> 13);        // N=8192 -> 2048 blocks

    main_kernel<<<blocks, 256>>>((const int4*)adj, outs, tgt, rowShift);
    epilogue_kernel<<<(N + 255) / 256, 256>>>(out, idx, N, K);
}

// round 8
// speedup vs baseline: 1.1890x; 1.1890x over previous
#include <cuda_runtime.h>

#define NMAX 8192

// Scratch — zero-initialized at module load; reduce_kernel restores accumulator
// zeros after every call so graph replays see a clean state. g_contrib is
// overwritten every call, never cleaned.
__device__ int      g_cntpack[2][NMAX];   // low 16: cnt, high 16: pos_cnt
__device__ float    g_sumexp[2][NMAX];    // sum of exp(out[i]) over mask
__device__ float    g_poslog[2][NMAX];    // sum of out[i] over mask & pos
__device__ float    g_contrib[NMAX];      // per-column contribution (overwritten)
__device__ float    g_res;                // cross-block partial sum
__device__ unsigned g_done;               // block-completion counter

// Row-per-warp scan: each warp owns 1024 contiguous int4 quads (half a row at
// N=8192), so the row index, outs[i], targets[i], expf and pack are computed
// ONCE per warp (lane-uniform). Loads are fully coalesced (512B per LDG.128).
// Hits scatter into per-(side,column) accumulators on a short divergent path.
__global__ void __launch_bounds__(256) main_kernel(
    const int4* __restrict__ adj,
    const float* __restrict__ outs,
    const int* __restrict__ tgt,
    int rowShift)                          // log2(quads per row)
{
    const int  gtid  = blockIdx.x * blockDim.x + threadIdx.x;
    const int  gwarp = gtid >> 5;
    const int  lane  = gtid & 31;

    const long long quadBase = (long long)gwarp << 10;          // 1024 quads/warp
    const int i      = (int)(quadBase >> rowShift);             // row (warp-uniform)
    const int cqBase = (int)(quadBase & ((1 << rowShift) - 1)); // quad offset in row

    const float o    = __ldg(&outs[i]);                         // broadcast loads
    const int   p    = (__ldg(&tgt[i]) != 0) ? 1 : 0;
    const float e    = expf(o);
    const int   pack = 1 + (p << 16);

    #pragma unroll
    for (int jb = 0; jb < 4; jb++) {
        int4 vv[8];
        #pragma unroll
        for (int u = 0; u < 8; u++)
            vv[u] = __ldg(&adj[quadBase + (jb * 8 + u) * 32 + lane]);

        #pragma unroll
        for (int u = 0; u < 8; u++) {
            int4 v = vv[u];
            if ((v.x | v.y | v.z | v.w) == 0) continue;         // ~98.5% of quads

            int c = (cqBase + (jb * 8 + u) * 32 + lane) << 2;   // first column
            #pragma unroll
            for (int w = 0; w < 4; w++) {
                int val = (w == 0) ? v.x : (w == 1) ? v.y : (w == 2) ? v.z : v.w;
                int cc = c + w;
                if (val != 0 && cc != i) {
                    int side = (i < cc) ? 0 : 1;  // 0 = lower (i < k), 1 = upper
                    atomicAdd(&g_cntpack[side][cc], pack);
                    atomicAdd(&g_sumexp[side][cc], e);
                    if (p) atomicAdd(&g_poslog[side][cc], o);
                }
            }
        }
    }
}

// Per-column contribution: 6 independent loads, compute, overwrite g_contrib[c].
// No search, no clean, no reduction — single flat memory round-trip.
__global__ void __launch_bounds__(256) contrib_kernel(int N) {
    int c = blockIdx.x * blockDim.x + threadIdx.x;
    if (c >= N) return;

    int   pack0 = g_cntpack[0][c], pack1 = g_cntpack[1][c];
    float se0 = g_sumexp[0][c], se1 = g_sumexp[1][c];
    float pl0 = g_poslog[0][c], pl1 = g_poslog[1][c];

    int cnt0 = pack0 & 0xFFFF, pc0 = pack0 >> 16;
    int cnt1 = pack1 & 0xFFFF, pc1 = pack1 >> 16;

    float v = 0.f;
    if (cnt0 > 0 && pc0 == 1) v += (logf(se0) - pl0) / (float)cnt0;
    if (cnt1 > 0 && pc1 == 1) v += (logf(se1) - pl1) / (float)cnt1;
    g_contrib[c] = v;
}

// Gather g_contrib over idx entries — ONE gather per thread (duplicates in the
// sorted idx supply multiplicity for free), clean the accumulator arrays
// (disjoint from what we read), block-reduce, last block publishes out[0].
__global__ void __launch_bounds__(256) reduce_kernel(
    float* __restrict__ out,
    const int* __restrict__ idx,
    int N, int K)
{
    int t = blockIdx.x * blockDim.x + threadIdx.x;

    float local = 0.f;
    if (t < K) local = g_contrib[__ldg(&idx[t])];

    if (t < N) {   // self-clean accumulators for next replay (not g_contrib)
        g_cntpack[0][t] = 0; g_cntpack[1][t] = 0;
        g_sumexp[0][t] = 0.f; g_sumexp[1][t] = 0.f;
        g_poslog[0][t] = 0.f; g_poslog[1][t] = 0.f;
    }

    #pragma unroll
    for (int s = 16; s > 0; s >>= 1)
        local += __shfl_xor_sync(0xFFFFFFFF, local, s);

    __shared__ float warpsum[8];
    int lane = threadIdx.x & 31, wid = threadIdx.x >> 5;
    if (lane == 0) warpsum[wid] = local;
    __syncthreads();
    if (wid == 0) {
        float b = (lane < 8) ? warpsum[lane] : 0.f;
        #pragma unroll
        for (int s = 4; s > 0; s >>= 1)
            b += __shfl_xor_sync(0xFFFFFFFF, b, s);
        if (lane == 0) {
            atomicAdd(&g_res, b);
            __threadfence();
            unsigned d = atomicAdd(&g_done, 1u);
            if (d == gridDim.x - 1) {
                out[0] = atomicExch(&g_res, 0.f);
                g_done = 0;
            }
        }
    }
}

extern "C" void kernel_launch(void* const* d_in, const int* in_sizes, int n_in,
                              void* d_out, int out_size) {
    const float* outs = (const float*)d_in[0];   // outputs  [N] f32
    const int*   tgt  = (const int*)d_in[1];     // targets  [N] i32
    const int*   adj  = (const int*)d_in[2];     // node_adj [N,N] i32
    const int*   idx  = (const int*)d_in[3];     // idx_node [K] i32 (sorted)
    int N = in_sizes[0];
    int K = in_sizes[3];
    float* out = (float*)d_out;

    // quadsPerRow = N/4 is a power of two; rowShift = log2(N/4)
    int rowShift = 0;
    for (int t = N >> 2; t > 1; t >>= 1) rowShift++;

    // Each warp: 1024 quads; each block (8 warps): 8192 quads.
    long long totalQuads = ((long long)N * N) >> 2;
    int blocks = (int)(totalQuads >> 13);        // N=8192 -> 2048 blocks

    main_kernel<<<blocks, 256>>>((const int4*)adj, outs, tgt, rowShift);
    contrib_kernel<<<(N + 255) / 256, 256>>>(N);
    reduce_kernel<<<(N + 255) / 256, 256>>>(out, idx, N, K);
}

// round 9
// speedup vs baseline: 1.1913x; 1.0019x over previous
#include <cuda_runtime.h>

#define NMAX 8192

// Scratch — zero-initialized at module load; reduce_kernel restores accumulator
// zeros after every call so graph replays see a clean state. g_contrib is
// overwritten every call, never cleaned.
__device__ int      g_cntpack[2][NMAX];   // low 16: cnt, high 16: pos_cnt
__device__ float    g_sumexp[2][NMAX];    // sum of exp(out[i]) over mask
__device__ float    g_poslog[2][NMAX];    // sum of out[i] over mask & pos
__device__ float    g_contrib[NMAX];      // per-column contribution (overwritten)
__device__ float    g_res;                // cross-block partial sum
__device__ unsigned g_done;               // block-completion counter

// Row-per-warp scan: each warp owns 1024 contiguous int4 quads (half a row at
// N=8192) so row index, outs[i], targets[i], expf and pack are computed ONCE
// per warp (lane-uniform). Loads fully coalesced (512B per LDG.128).
// Batch x4 (not x8) to keep regs ~40 and allow 6 blocks/SM (75% occupancy).
__global__ void __launch_bounds__(256, 6) main_kernel(
    const int4* __restrict__ adj,
    const float* __restrict__ outs,
    const int* __restrict__ tgt,
    int rowShift)                          // log2(quads per row)
{
    const int  gtid  = blockIdx.x * blockDim.x + threadIdx.x;
    const int  gwarp = gtid >> 5;
    const int  lane  = gtid & 31;

    const long long quadBase = (long long)gwarp << 10;          // 1024 quads/warp
    const int i      = (int)(quadBase >> rowShift);             // row (warp-uniform)
    const int cqBase = (int)(quadBase & ((1 << rowShift) - 1)); // quad offset in row

    const float o    = __ldg(&outs[i]);                         // broadcast loads
    const int   p    = (__ldg(&tgt[i]) != 0) ? 1 : 0;
    const float e    = expf(o);
    const int   pack = 1 + (p << 16);

    const int4* ptr  = adj + quadBase + lane;
    int cBase        = (cqBase + lane) << 2;                    // column of ptr[0]

    #pragma unroll
    for (int jb = 0; jb < 8; jb++) {
        int4 v0 = __ldg(ptr);
        int4 v1 = __ldg(ptr + 32);
        int4 v2 = __ldg(ptr + 64);
        int4 v3 = __ldg(ptr + 96);

        #pragma unroll
        for (int u = 0; u < 4; u++) {
            int4 v = (u == 0) ? v0 : (u == 1) ? v1 : (u == 2) ? v2 : v3;
            if ((v.x | v.y | v.z | v.w) == 0) continue;         // ~98.5% of quads

            int c = cBase + (u << 7);                           // +u*32 quads *4 cols
            #pragma unroll
            for (int w = 0; w < 4; w++) {
                int val = (w == 0) ? v.x : (w == 1) ? v.y : (w == 2) ? v.z : v.w;
                int cc = c + w;
                if (val != 0 && cc != i) {
                    int side = (i < cc) ? 0 : 1;  // 0 = lower (i < k), 1 = upper
                    atomicAdd(&g_cntpack[side][cc], pack);
                    atomicAdd(&g_sumexp[side][cc], e);
                    if (p) atomicAdd(&g_poslog[side][cc], o);
                }
            }
        }
        ptr   += 128;          // 4 batches of 32 quads consumed
        cBase += 128 << 2;
    }
}

// Per-column contribution: 6 independent loads, compute, overwrite g_contrib[c].
// No search, no clean, no reduction — single flat memory round-trip.
__global__ void __launch_bounds__(256) contrib_kernel(int N) {
    int c = blockIdx.x * blockDim.x + threadIdx.x;
    if (c >= N) return;

    int   pack0 = g_cntpack[0][c], pack1 = g_cntpack[1][c];
    float se0 = g_sumexp[0][c], se1 = g_sumexp[1][c];
    float pl0 = g_poslog[0][c], pl1 = g_poslog[1][c];

    int cnt0 = pack0 & 0xFFFF, pc0 = pack0 >> 16;
    int cnt1 = pack1 & 0xFFFF, pc1 = pack1 >> 16;

    float v = 0.f;
    if (cnt0 > 0 && pc0 == 1) v += (logf(se0) - pl0) / (float)cnt0;
    if (cnt1 > 0 && pc1 == 1) v += (logf(se1) - pl1) / (float)cnt1;
    g_contrib[c] = v;
}

// Gather g_contrib over idx entries — ONE gather per thread (duplicates in the
// sorted idx supply multiplicity for free), clean the accumulator arrays
// (disjoint from what we read), block-reduce, last block publishes out[0].
__global__ void __launch_bounds__(256) reduce_kernel(
    float* __restrict__ out,
    const int* __restrict__ idx,
    int N, int K)
{
    int t = blockIdx.x * blockDim.x + threadIdx.x;

    float local = 0.f;
    if (t < K) local = g_contrib[__ldg(&idx[t])];

    if (t < N) {   // self-clean accumulators for next replay (not g_contrib)
        g_cntpack[0][t] = 0; g_cntpack[1][t] = 0;
        g_sumexp[0][t] = 0.f; g_sumexp[1][t] = 0.f;
        g_poslog[0][t] = 0.f; g_poslog[1][t] = 0.f;
    }

    #pragma unroll
    for (int s = 16; s > 0; s >>= 1)
        local += __shfl_xor_sync(0xFFFFFFFF, local, s);

    __shared__ float warpsum[8];
    int lane = threadIdx.x & 31, wid = threadIdx.x >> 5;
    if (lane == 0) warpsum[wid] = local;
    __syncthreads();
    if (wid == 0) {
        float b = (lane < 8) ? warpsum[lane] : 0.f;
        #pragma unroll
        for (int s = 4; s > 0; s >>= 1)
            b += __shfl_xor_sync(0xFFFFFFFF, b, s);
        if (lane == 0) {
            atomicAdd(&g_res, b);
            __threadfence();
            unsigned d = atomicAdd(&g_done, 1u);
            if (d == gridDim.x - 1) {
                out[0] = atomicExch(&g_res, 0.f);
                g_done = 0;
            }
        }
    }
}

extern "C" void kernel_launch(void* const* d_in, const int* in_sizes, int n_in,
                              void* d_out, int out_size) {
    const float* outs = (const float*)d_in[0];   // outputs  [N] f32
    const int*   tgt  = (const int*)d_in[1];     // targets  [N] i32
    const int*   adj  = (const int*)d_in[2];     // node_adj [N,N] i32
    const int*   idx  = (const int*)d_in[3];     // idx_node [K] i32 (sorted)
    int N = in_sizes[0];
    int K = in_sizes[3];
    float* out = (float*)d_out;

    // quadsPerRow = N/4 is a power of two; rowShift = log2(N/4)
    int rowShift = 0;
    for (int t = N >> 2; t > 1; t >>= 1) rowShift++;

    // Each warp: 1024 quads; each block (8 warps): 8192 quads.
    long long totalQuads = ((long long)N * N) >> 2;
    int blocks = (int)(totalQuads >> 13);        // N=8192 -> 2048 blocks

    main_kernel<<<blocks, 256>>>((const int4*)adj, outs, tgt, rowShift);
    contrib_kernel<<<(N + 255) / 256, 256>>>(N);
    reduce_kernel<<<(N + 255) / 256, 256>>>(out, idx, N, K);
}

// round 10
// speedup vs baseline: 1.2321x; 1.0343x over previous
#include <cuda_runtime.h>

#define NMAX 8192

// Scratch — zero-initialized at module load; reduce_kernel restores accumulator
// zeros after every call so graph replays see a clean state. g_contrib is
// overwritten every call, never cleaned.
__device__ int      g_cntpack[2][NMAX];   // low 16: cnt, high 16: pos_cnt
__device__ float    g_sumexp[2][NMAX];    // sum of exp(out[i]) over mask
__device__ float    g_poslog[2][NMAX];    // sum of out[i] over mask & pos
__device__ float    g_contrib[NMAX];      // per-column contribution (overwritten)
__device__ float    g_res;                // cross-block partial sum
__device__ unsigned g_done;               // block-completion counter

// Row-per-warp scan: each warp owns 1024 contiguous int4 quads (half a row at
// N=8192) so row index, outs[i], targets[i], expf and pack are computed ONCE
// per warp (lane-uniform). Loads fully coalesced (512B per LDG.128), streamed
// with evict-first policy (__ldcs) so the read-once 256MB doesn't evict the
// hot accumulator lines from L2. A single merged zero-test skips each 512B
// batch (~94% of batches) with one branch.
__global__ void __launch_bounds__(256, 6) main_kernel(
    const int4* __restrict__ adj,
    const float* __restrict__ outs,
    const int* __restrict__ tgt,
    int rowShift)                          // log2(quads per row)
{
    const int  gtid  = blockIdx.x * blockDim.x + threadIdx.x;
    const int  gwarp = gtid >> 5;
    const int  lane  = gtid & 31;

    const long long quadBase = (long long)gwarp << 10;          // 1024 quads/warp
    const int i      = (int)(quadBase >> rowShift);             // row (warp-uniform)
    const int cqBase = (int)(quadBase & ((1 << rowShift) - 1)); // quad offset in row

    const float o    = __ldg(&outs[i]);                         // broadcast loads
    const int   p    = (__ldg(&tgt[i]) != 0) ? 1 : 0;
    const float e    = expf(o);
    const int   pack = 1 + (p << 16);

    const int4* ptr  = adj + quadBase + lane;
    int cBase        = (cqBase + lane) << 2;                    // column of ptr[0]

    #pragma unroll
    for (int jb = 0; jb < 8; jb++) {
        int4 v0 = __ldcs(ptr);
        int4 v1 = __ldcs(ptr + 32);
        int4 v2 = __ldcs(ptr + 64);
        int4 v3 = __ldcs(ptr + 96);

        int any = (v0.x | v0.y | v0.z | v0.w) | (v1.x | v1.y | v1.z | v1.w)
                | (v2.x | v2.y | v2.z | v2.w) | (v3.x | v3.y | v3.z | v3.w);

        if (any != 0) {                                          // ~6% of batches
            #pragma unroll
            for (int u = 0; u < 4; u++) {
                int4 v = (u == 0) ? v0 : (u == 1) ? v1 : (u == 2) ? v2 : v3;
                if ((v.x | v.y | v.z | v.w) == 0) continue;

                int c = cBase + (u << 7);                        // +u*32 quads *4 cols
                #pragma unroll
                for (int w = 0; w < 4; w++) {
                    int val = (w == 0) ? v.x : (w == 1) ? v.y : (w == 2) ? v.z : v.w;
                    int cc = c + w;
                    if (val != 0 && cc != i) {
                        int side = (i < cc) ? 0 : 1;  // 0 = lower (i<k), 1 = upper
                        atomicAdd(&g_cntpack[side][cc], pack);
                        atomicAdd(&g_sumexp[side][cc], e);
                        if (p) atomicAdd(&g_poslog[side][cc], o);
                    }
                }
            }
        }
        ptr   += 128;          // 4 batches of 32 quads consumed
        cBase += 128 << 2;
    }
}

// Per-column contribution: 6 independent loads, compute, overwrite g_contrib[c].
// No search, no clean, no reduction — single flat memory round-trip.
__global__ void __launch_bounds__(256) contrib_kernel(int N) {
    int c = blockIdx.x * blockDim.x + threadIdx.x;
    if (c >= N) return;

    int   pack0 = g_cntpack[0][c], pack1 = g_cntpack[1][c];
    float se0 = g_sumexp[0][c], se1 = g_sumexp[1][c];
    float pl0 = g_poslog[0][c], pl1 = g_poslog[1][c];

    int cnt0 = pack0 & 0xFFFF, pc0 = pack0 >> 16;
    int cnt1 = pack1 & 0xFFFF, pc1 = pack1 >> 16;

    float v = 0.f;
    if (cnt0 > 0 && pc0 == 1) v += (logf(se0) - pl0) / (float)cnt0;
    if (cnt1 > 0 && pc1 == 1) v += (logf(se1) - pl1) / (float)cnt1;
    g_contrib[c] = v;
}

// Gather g_contrib over idx entries — ONE gather per thread (duplicates in the
// sorted idx supply multiplicity for free), clean the accumulator arrays
// (disjoint from what we read), block-reduce, last block publishes out[0].
__global__ void __launch_bounds__(256) reduce_kernel(
    float* __restrict__ out,
    const int* __restrict__ idx,
    int N, int K)
{
    int t = blockIdx.x * blockDim.x + threadIdx.x;

    float local = 0.f;
    if (t < K) local = g_contrib[__ldg(&idx[t])];

    if (t < N) {   // self-clean accumulators for next replay (not g_contrib)
        g_cntpack[0][t] = 0; g_cntpack[1][t] = 0;
        g_sumexp[0][t] = 0.f; g_sumexp[1][t] = 0.f;
        g_poslog[0][t] = 0.f; g_poslog[1][t] = 0.f;
    }

    #pragma unroll
    for (int s = 16; s > 0; s >>= 1)
        local += __shfl_xor_sync(0xFFFFFFFF, local, s);

    __shared__ float warpsum[8];
    int lane = threadIdx.x & 31, wid = threadIdx.x >> 5;
    if (lane == 0) warpsum[wid] = local;
    __syncthreads();
    if (wid == 0) {
        float b = (lane < 8) ? warpsum[lane] : 0.f;
        #pragma unroll
        for (int s = 4; s > 0; s >>= 1)
            b += __shfl_xor_sync(0xFFFFFFFF, b, s);
        if (lane == 0) {
            atomicAdd(&g_res, b);
            __threadfence();
            unsigned d = atomicAdd(&g_done, 1u);
            if (d == gridDim.x - 1) {
                out[0] = atomicExch(&g_res, 0.f);
                g_done = 0;
            }
        }
    }
}

extern "C" void kernel_launch(void* const* d_in, const int* in_sizes, int n_in,
                              void* d_out, int out_size) {
    const float* outs = (const float*)d_in[0];   // outputs  [N] f32
    const int*   tgt  = (const int*)d_in[1];     // targets  [N] i32
    const int*   adj  = (const int*)d_in[2];     // node_adj [N,N] i32
    const int*   idx  = (const int*)d_in[3];     // idx_node [K] i32 (sorted)
    int N = in_sizes[0];
    int K = in_sizes[3];
    float* out = (float*)d_out;

    // quadsPerRow = N/4 is a power of two; rowShift = log2(N/4)
    int rowShift = 0;
    for (int t = N >> 2; t > 1; t >>= 1) rowShift++;

    // Each warp: 1024 quads; each block (8 warps): 8192 quads.
    long long totalQuads = ((long long)N * N) >> 2;
    int blocks = (int)(totalQuads >> 13);        // N=8192 -> 2048 blocks

    main_kernel<<<blocks, 256>>>((const int4*)adj, outs, tgt, rowShift);
    contrib_kernel<<<(N + 255) / 256, 256>>>(N);
    reduce_kernel<<<(N + 255) / 256, 256>>>(out, idx, N, K);
}